// round 5
// baseline (speedup 1.0000x reference)
#include <cuda_runtime.h>
#include <math.h>

#define N_RNA  4096
#define N_ATAC 8192
#define IN_C   256
#define HID    128
#define NHEAD  2
#define DH     64
#define TOPK   10
#define THR    0.8f

// ---------------- device scratch (statically allocated; no cudaMalloc) -----
__device__ float g_q   [N_RNA  * HID];
__device__ float g_k   [N_ATAC * HID];
__device__ float g_vr  [N_RNA  * HID];
__device__ float g_va  [N_ATAC * HID];
__device__ float g_S   [(size_t)NHEAD * N_RNA * N_ATAC];   // 256 MB masked scores
__device__ float g_ragg[N_RNA  * HID];
__device__ float g_aagg[N_ATAC * HID];
__device__ float g_catr[N_RNA  * 2 * HID];
__device__ float g_cata[N_ATAC * 2 * HID];

// ---------------- zero atac aggregation buffer -----------------------------
__global__ void zero_aagg_kernel() {
    int i = blockIdx.x * blockDim.x + threadIdx.x;            // 262144 float4
    float4 z = make_float4(0.f, 0.f, 0.f, 0.f);
    reinterpret_cast<float4*>(g_aagg)[i] = z;
}

// ---------------- generic GEMM: C[N x 128] = X[N x K] @ W[K x 128] + b -----
// BM = 32 rows per block, 256 threads, micro-tile 4x4. grid.x = N/32.
#define GBK 16
__global__ __launch_bounds__(256)
void gemm_bias_kernel(const float* __restrict__ X, int K,
                      const float* __restrict__ W,
                      const float* __restrict__ b,
                      float* __restrict__ C, int ldc)
{
    __shared__ float Xs[GBK * 36];     // [kk][row], padded to 36
    __shared__ float Ws[GBK * 128];    // [kk][col]
    const int t   = threadIdx.x;
    const int r0  = blockIdx.x * 32;
    const int rg4 = (t >> 5) * 4;      // row base within tile (per-warp uniform)
    const int cg  = (t & 31) * 4;      // col base

    float acc[4][4];
#pragma unroll
    for (int i = 0; i < 4; i++)
#pragma unroll
        for (int j = 0; j < 4; j++) acc[i][j] = 0.f;

    for (int k0 = 0; k0 < K; k0 += GBK) {
        // load X tile 32x16 (512 elems, 2 per thread), transposed into Xs
#pragma unroll
        for (int i = 0; i < 2; i++) {
            int idx = t + i * 256;
            int row = idx >> 4;
            int kk  = idx & 15;
            Xs[kk * 36 + row] = X[(size_t)(r0 + row) * K + k0 + kk];
        }
        // load W tile 16x128 (2048 elems, 8 per thread via float4)
#pragma unroll
        for (int i = 0; i < 2; i++) {
            int row = (t >> 5) + i * 8;
            int col = (t & 31) * 4;
            float4 w4 = *reinterpret_cast<const float4*>(&W[(size_t)(k0 + row) * 128 + col]);
            *reinterpret_cast<float4*>(&Ws[row * 128 + col]) = w4;
        }
        __syncthreads();
#pragma unroll
        for (int kk = 0; kk < GBK; kk++) {
            float4 wv = *reinterpret_cast<const float4*>(&Ws[kk * 128 + cg]);
            float4 xv = *reinterpret_cast<const float4*>(&Xs[kk * 36 + rg4]);
            acc[0][0] += xv.x * wv.x; acc[0][1] += xv.x * wv.y; acc[0][2] += xv.x * wv.z; acc[0][3] += xv.x * wv.w;
            acc[1][0] += xv.y * wv.x; acc[1][1] += xv.y * wv.y; acc[1][2] += xv.y * wv.z; acc[1][3] += xv.y * wv.w;
            acc[2][0] += xv.z * wv.x; acc[2][1] += xv.z * wv.y; acc[2][2] += xv.z * wv.z; acc[2][3] += xv.z * wv.w;
            acc[3][0] += xv.w * wv.x; acc[3][1] += xv.w * wv.y; acc[3][2] += xv.w * wv.z; acc[3][3] += xv.w * wv.w;
        }
        __syncthreads();
    }
    float4 bb = *reinterpret_cast<const float4*>(&b[cg]);
#pragma unroll
    for (int i = 0; i < 4; i++) {
        int r = r0 + rg4 + i;
        float4 o = make_float4(acc[i][0] + bb.x, acc[i][1] + bb.y,
                               acc[i][2] + bb.z, acc[i][3] + bb.w);
        *reinterpret_cast<float4*>(&C[(size_t)r * ldc + cg]) = o;
    }
}

// ---------------- masked score GEMM: S[h][r][a] = (q[r,h,:].k[a,h,:]) * mask
// tile: 64 rows (r) x 128 cols (a), K = 64. grid = (64, 64, 2). 256 threads.
// dynamic smem: qs[64][68] (transposed [d][r]), ks[64][132] ([d][a]).
__global__ __launch_bounds__(256)
void scores_kernel(const float* __restrict__ mask)
{
    extern __shared__ float smem[];
    float* qs = smem;               // 64*68  = 4352 floats
    float* ks = smem + 64 * 68;     // 64*132 = 8448 floats

    const int t  = threadIdx.x;
    const int a0 = blockIdx.x * 128;
    const int r0 = blockIdx.y * 64;
    const int h  = blockIdx.z;

    // load q tile (64 rows x 64 d) transposed
#pragma unroll
    for (int i = 0; i < 4; i++) {
        int idx = t + i * 256;                      // 0..1023
        int r   = idx >> 4;
        int c4  = (idx & 15) * 4;
        float4 v = *reinterpret_cast<const float4*>(&g_q[(size_t)(r0 + r) * HID + h * DH + c4]);
        qs[(c4 + 0) * 68 + r] = v.x;
        qs[(c4 + 1) * 68 + r] = v.y;
        qs[(c4 + 2) * 68 + r] = v.z;
        qs[(c4 + 3) * 68 + r] = v.w;
    }
    // load k tile (128 rows x 64 d) transposed
#pragma unroll
    for (int i = 0; i < 8; i++) {
        int idx = t + i * 256;                      // 0..2047
        int a   = idx >> 4;
        int c4  = (idx & 15) * 4;
        float4 v = *reinterpret_cast<const float4*>(&g_k[(size_t)(a0 + a) * HID + h * DH + c4]);
        ks[(c4 + 0) * 132 + a] = v.x;
        ks[(c4 + 1) * 132 + a] = v.y;
        ks[(c4 + 2) * 132 + a] = v.z;
        ks[(c4 + 3) * 132 + a] = v.w;
    }
    __syncthreads();

    const int rg = (t >> 5) * 8;    // row base (per-warp uniform -> broadcast LDS)
    const int cg = (t & 31) * 4;    // col base

    float acc[8][4];
#pragma unroll
    for (int i = 0; i < 8; i++)
#pragma unroll
        for (int j = 0; j < 4; j++) acc[i][j] = 0.f;

#pragma unroll 16
    for (int d = 0; d < 64; d++) {
        float4 k4 = *reinterpret_cast<const float4*>(&ks[d * 132 + cg]);
        float4 qa = *reinterpret_cast<const float4*>(&qs[d * 68 + rg]);
        float4 qb = *reinterpret_cast<const float4*>(&qs[d * 68 + rg + 4]);
        acc[0][0] += qa.x * k4.x; acc[0][1] += qa.x * k4.y; acc[0][2] += qa.x * k4.z; acc[0][3] += qa.x * k4.w;
        acc[1][0] += qa.y * k4.x; acc[1][1] += qa.y * k4.y; acc[1][2] += qa.y * k4.z; acc[1][3] += qa.y * k4.w;
        acc[2][0] += qa.z * k4.x; acc[2][1] += qa.z * k4.y; acc[2][2] += qa.z * k4.z; acc[2][3] += qa.z * k4.w;
        acc[3][0] += qa.w * k4.x; acc[3][1] += qa.w * k4.y; acc[3][2] += qa.w * k4.z; acc[3][3] += qa.w * k4.w;
        acc[4][0] += qb.x * k4.x; acc[4][1] += qb.x * k4.y; acc[4][2] += qb.x * k4.z; acc[4][3] += qb.x * k4.w;
        acc[5][0] += qb.y * k4.x; acc[5][1] += qb.y * k4.y; acc[5][2] += qb.y * k4.z; acc[5][3] += qb.y * k4.w;
        acc[6][0] += qb.z * k4.x; acc[6][1] += qb.z * k4.y; acc[6][2] += qb.z * k4.z; acc[6][3] += qb.z * k4.w;
        acc[7][0] += qb.w * k4.x; acc[7][1] += qb.w * k4.y; acc[7][2] += qb.w * k4.z; acc[7][3] += qb.w * k4.w;
    }

    const size_t Sbase = (size_t)h * N_RNA * N_ATAC;
#pragma unroll
    for (int i = 0; i < 8; i++) {
        int r = r0 + rg + i;
        float4 m4 = *reinterpret_cast<const float4*>(&mask[(size_t)r * N_ATAC + a0 + cg]);
        float4 o = make_float4(acc[i][0] * m4.x, acc[i][1] * m4.y,
                               acc[i][2] * m4.z, acc[i][3] * m4.w);
        *reinterpret_cast<float4*>(&g_S[Sbase + (size_t)r * N_ATAC + a0 + cg]) = o;
    }
}

// ---------------- top-k + softmax + gate + both aggregations ---------------
// one block per (r, h). 256 threads.
__global__ __launch_bounds__(256)
void topk_kernel()
{
    __shared__ float srow[N_ATAC];          // 32 KB
    __shared__ float redv[8];
    __shared__ int   redi[8];
    __shared__ float topv[TOPK];
    __shared__ int   topi[TOPK];
    __shared__ float wsel[TOPK];

    const int r = blockIdx.x;
    const int h = blockIdx.y;
    const int t = threadIdx.x;

    const float* Srow = &g_S[((size_t)h * N_RNA + r) * N_ATAC];
    for (int i = t * 4; i < N_ATAC; i += 1024)
        *reinterpret_cast<float4*>(&srow[i]) = *reinterpret_cast<const float4*>(&Srow[i]);
    __syncthreads();

    // 10 iterations of block argmax (ties -> lowest index, matching lax.top_k)
    for (int sel = 0; sel < TOPK; sel++) {
        float bv = -INFINITY;
        int   bi = N_ATAC;
        for (int i = t; i < N_ATAC; i += 256) {
            float v = srow[i];
            if (v > bv) { bv = v; bi = i; }
        }
#pragma unroll
        for (int off = 16; off > 0; off >>= 1) {
            float ov = __shfl_down_sync(0xffffffffu, bv, off);
            int   oi = __shfl_down_sync(0xffffffffu, bi, off);
            if (ov > bv || (ov == bv && oi < bi)) { bv = ov; bi = oi; }
        }
        if ((t & 31) == 0) { redv[t >> 5] = bv; redi[t >> 5] = bi; }
        __syncthreads();
        if (t == 0) {
            bv = redv[0]; bi = redi[0];
#pragma unroll
            for (int w = 1; w < 8; w++)
                if (redv[w] > bv || (redv[w] == bv && redi[w] < bi)) { bv = redv[w]; bi = redi[w]; }
            topv[sel] = bv; topi[sel] = bi;
            srow[bi] = -INFINITY;
        }
        __syncthreads();
    }

    // softmax over sigmoid(top scores), gate at > 0.8
    if (t == 0) {
        float p[TOPK], e[TOPK];
        float mx = -1e30f;
#pragma unroll
        for (int j = 0; j < TOPK; j++) {
            p[j] = 1.f / (1.f + expf(-topv[j]));
            if (p[j] > mx) mx = p[j];
        }
        float s = 0.f;
#pragma unroll
        for (int j = 0; j < TOPK; j++) { e[j] = expf(p[j] - mx); s += e[j]; }
#pragma unroll
        for (int j = 0; j < TOPK; j++) {
            float w = e[j] / s;
            if (!(p[j] > THR)) w = 0.f;
            wsel[j] = w;
        }
    }
    __syncthreads();

    if (t < DH) {
        // rna_agg[r,h,d] = sum_j w_j * v_a[idx_j, h, d]
        float accd = 0.f;
        float vr = g_vr[(size_t)r * HID + h * DH + t];
#pragma unroll
        for (int j = 0; j < TOPK; j++) {
            float w = wsel[j];
            int   a = topi[j];
            if (w != 0.f) {
                accd += w * g_va[(size_t)a * HID + h * DH + t];
                atomicAdd(&g_aagg[(size_t)a * HID + h * DH + t], w * vr);
            }
        }
        g_ragg[(size_t)r * HID + h * DH + t] = accd;
    }
}

// ---------------------------------------------------------------------------
extern "C" void kernel_launch(void* const* d_in, const int* in_sizes, int n_in,
                              void* d_out, int out_size)
{
    const float* x_rna  = (const float*)d_in[0];
    const float* x_atac = (const float*)d_in[1];
    const float* cmask  = (const float*)d_in[2];
    const float* Wq  = (const float*)d_in[3];  const float* bq  = (const float*)d_in[4];
    const float* Wk  = (const float*)d_in[5];  const float* bk  = (const float*)d_in[6];
    const float* Wvr = (const float*)d_in[7];  const float* bvr = (const float*)d_in[8];
    const float* Wva = (const float*)d_in[9];  const float* bva = (const float*)d_in[10];
    const float* Wor = (const float*)d_in[11]; const float* bor = (const float*)d_in[12];
    const float* Woa = (const float*)d_in[13]; const float* boa = (const float*)d_in[14];
    const float* Wsr = (const float*)d_in[15]; const float* bsr = (const float*)d_in[16];
    const float* Wsa = (const float*)d_in[17]; const float* bsa = (const float*)d_in[18];
    const float* Wdr = (const float*)d_in[19]; const float* bdr = (const float*)d_in[20];
    const float* Wda = (const float*)d_in[21]; const float* bda = (const float*)d_in[22];
    float* out = (float*)d_out;

    float *q_p, *k_p, *vr_p, *va_p, *ragg_p, *aagg_p, *catr_p, *cata_p;
    cudaGetSymbolAddress((void**)&q_p,    g_q);
    cudaGetSymbolAddress((void**)&k_p,    g_k);
    cudaGetSymbolAddress((void**)&vr_p,   g_vr);
    cudaGetSymbolAddress((void**)&va_p,   g_va);
    cudaGetSymbolAddress((void**)&ragg_p, g_ragg);
    cudaGetSymbolAddress((void**)&aagg_p, g_aagg);
    cudaGetSymbolAddress((void**)&catr_p, g_catr);
    cudaGetSymbolAddress((void**)&cata_p, g_cata);

    zero_aagg_kernel<<<1024, 256>>>();

    // projections
    gemm_bias_kernel<<<N_RNA  / 32, 256>>>(x_rna,  IN_C, Wq,  bq,  q_p,  HID);
    gemm_bias_kernel<<<N_ATAC / 32, 256>>>(x_atac, IN_C, Wk,  bk,  k_p,  HID);
    gemm_bias_kernel<<<N_ATAC / 32, 256>>>(x_atac, IN_C, Wva, bva, va_p, HID);
    gemm_bias_kernel<<<N_RNA  / 32, 256>>>(x_rna,  IN_C, Wvr, bvr, vr_p, HID);
    // self-attention parts go straight into the right halves of the concat buffers
    gemm_bias_kernel<<<N_RNA  / 32, 256>>>(x_rna,  IN_C, Wsr, bsr, catr_p + HID, 2 * HID);
    gemm_bias_kernel<<<N_ATAC / 32, 256>>>(x_atac, IN_C, Wsa, bsa, cata_p + HID, 2 * HID);

    // masked scores
    cudaFuncSetAttribute(scores_kernel, cudaFuncAttributeMaxDynamicSharedMemorySize, 51200);
    scores_kernel<<<dim3(N_ATAC / 128, N_RNA / 64, NHEAD), 256, 51200>>>(cmask);

    // top-k + softmax + gate + aggregation
    topk_kernel<<<dim3(N_RNA, NHEAD), 256>>>();

    // output projections + concat + dim reduction
    gemm_bias_kernel<<<N_RNA  / 32, 256>>>(ragg_p, HID, Wor, bor, catr_p, 2 * HID);
    gemm_bias_kernel<<<N_ATAC / 32, 256>>>(aagg_p, HID, Woa, boa, cata_p, 2 * HID);
    gemm_bias_kernel<<<N_RNA  / 32, 256>>>(catr_p, 2 * HID, Wdr, bdr, out, HID);
    gemm_bias_kernel<<<N_ATAC / 32, 256>>>(cata_p, 2 * HID, Wda, bda, out + (size_t)N_RNA * HID, HID);
}